// round 15
// baseline (speedup 1.0000x reference)
#include <cuda_runtime.h>
#include <cuda_fp16.h>
#include <cstdint>
#include <math.h>

// ---------------------------------------------------------------------------
// ExpertRouter: h = silu(x@W1+b1); logits = h@W2+b2; top-2 softmax + aux loss.
// B=16384, D=4096, HID=2048, E=64.
// GEMM1 (fp16 mma, CTA 128x256, 3-stage cp.async, single-sync) FUSES the
// logit GEMM: h never hits gmem; per-CTA partial logits -> g_plog[8][B][64].
// router_reduce sums slices + top2/softmax/stats. Near-tie rows (gap < TAU)
// recomputed exactly in fp32 via compact g_Hfix (indices exact).
// Output layout (f32): [weights B*2 | top_idx(as float) B*2 | aux].
// ---------------------------------------------------------------------------

#define Bdim 16384
#define Ddim 4096
#define HIDd 2048
#define Ed   64
#define NSLC (HIDd / 256)        // 8 column slices
#define TAU  4e-3f
#define FIXCAP 4096

__device__ __half g_xh[(size_t)Bdim * Ddim];    // 134 MB x in fp16
__device__ __half g_W1h[(size_t)HIDd * Ddim];   // 16.8 MB W1^T in fp16
__device__ float  g_plog[(size_t)NSLC * Bdim * Ed]; // 33.5 MB partial logits
__device__ float  g_Hfix[(size_t)FIXCAP * HIDd];    // 33.5 MB exact h (flagged)
__device__ float  g_pprob[512 * Ed];
__device__ int    g_top1[Bdim];
__device__ int    g_fixcount;
__device__ int    g_fixlist[FIXCAP];

// ---- helpers ----
__device__ __forceinline__ float silu_f(float v) { return v / (1.0f + expf(-v)); }

__device__ __forceinline__ uint32_t smem_u32(const void* p) {
    uint32_t a;
    asm("{ .reg .u64 t; cvta.to.shared.u64 t, %1; cvt.u32.u64 %0, t; }" : "=r"(a) : "l"(p));
    return a;
}
__device__ __forceinline__ void cp_async16(uint32_t saddr, const void* gaddr) {
    asm volatile("cp.async.cg.shared.global [%0], [%1], 16;" :: "r"(saddr), "l"(gaddr));
}
__device__ __forceinline__ void cp_commit() {
    asm volatile("cp.async.commit_group;");
}
template <int N>
__device__ __forceinline__ void cp_wait() {
    asm volatile("cp.async.wait_group %0;" :: "n"(N));
}
__device__ __forceinline__ void ldsm_x4(uint32_t r[4], uint32_t saddr) {
    asm volatile("ldmatrix.sync.aligned.m8n8.x4.shared.b16 {%0,%1,%2,%3}, [%4];"
                 : "=r"(r[0]), "=r"(r[1]), "=r"(r[2]), "=r"(r[3]) : "r"(saddr));
}
__device__ __forceinline__ void mma_fp16(float c[4], const uint32_t a[4],
                                         uint32_t b0, uint32_t b1) {
    asm("mma.sync.aligned.m16n8k16.row.col.f32.f16.f16.f32 "
        "{%0,%1,%2,%3}, {%4,%5,%6,%7}, {%8,%9}, {%0,%1,%2,%3};"
        : "+f"(c[0]), "+f"(c[1]), "+f"(c[2]), "+f"(c[3])
        : "r"(a[0]), "r"(a[1]), "r"(a[2]), "r"(a[3]), "r"(b0), "r"(b1));
}

// ---- packed f32x2 ----
__device__ __forceinline__ unsigned long long pack2(float lo, float hi) {
    unsigned long long r;
    asm("mov.b64 %0, {%1, %2};" : "=l"(r) : "f"(lo), "f"(hi));
    return r;
}
__device__ __forceinline__ unsigned long long fma2(unsigned long long a,
                                                   unsigned long long b,
                                                   unsigned long long c) {
    unsigned long long d;
    asm("fma.rn.f32x2 %0, %1, %2, %3;" : "=l"(d) : "l"(a), "l"(b), "l"(c));
    return d;
}
__device__ __forceinline__ float2 unpack2(unsigned long long v) {
    float2 f;
    asm("mov.b64 {%0, %1}, %2;" : "=f"(f.x), "=f"(f.y) : "l"(v));
    return f;
}

// ---------------------------------------------------------------------------
__global__ __launch_bounds__(256)
void cvt_x(const float* __restrict__ x) {
    if (blockIdx.x == 0 && threadIdx.x == 0) g_fixcount = 0;
    size_t i = ((size_t)blockIdx.x * 256 + threadIdx.x) * 8;
    float4 f0 = *(const float4*)(x + i);
    float4 f1 = *(const float4*)(x + i + 4);
    __half2 h0 = __floats2half2_rn(f0.x, f0.y);
    __half2 h1 = __floats2half2_rn(f0.z, f0.w);
    __half2 h2 = __floats2half2_rn(f1.x, f1.y);
    __half2 h3 = __floats2half2_rn(f1.z, f1.w);
    uint4 o;
    o.x = *(uint32_t*)&h0; o.y = *(uint32_t*)&h1;
    o.z = *(uint32_t*)&h2; o.w = *(uint32_t*)&h3;
    *(uint4*)(g_xh + i) = o;
}

// ---------------------------------------------------------------------------
__global__ __launch_bounds__(256)
void transpose_W1h(const float* __restrict__ W1) {
    __shared__ float s[32][33];
    const int n0 = blockIdx.x * 32;
    const int k0 = blockIdx.y * 32;
    const int tx = threadIdx.x & 31;
    const int ty = (threadIdx.x >> 5) * 4;
#pragma unroll
    for (int i = 0; i < 4; i++)
        s[ty + i][tx] = W1[(size_t)(k0 + ty + i) * HIDd + n0 + tx];
    __syncthreads();
#pragma unroll
    for (int i = 0; i < 4; i++)
        g_W1h[(size_t)(n0 + ty + i) * Ddim + k0 + tx] = __float2half_rn(s[tx][ty + i]);
}

// ---------------------------------------------------------------------------
// GEMM1 + fused logits. CTA 128m x 256n, 16 warps (4m x 4n), warp 32x64,
// BK=64, cp.async 3-stage (single sync), ldmatrix. Epilogue: h->smem fp16,
// W2 slice->smem, tensor-core [128x64x256] partial-logit GEMM -> g_plog.
// ---------------------------------------------------------------------------
#define BKh 64
#define LDAh 72                         // halves per row (144 B)
#define A_H (128 * LDAh)
#define B_H (256 * LDAh)
#define STG_H (A_H + B_H)               // 27648 halves per stage
#define NSTAGE 3
#define SMEM_G1 (NSTAGE * STG_H * 2)    // 165888 bytes
#define LDAe 264                        // epilogue row stride (528 B)

__global__ __launch_bounds__(512, 1)
void gemm1_fused(const float* __restrict__ b1,
                 const float* __restrict__ W2) {
    extern __shared__ __half smh[];
    const uint32_t sbase = smem_u32(smh);

    const int tid = threadIdx.x;
    const int wid = tid >> 5, lane = tid & 31;
    const int rowBase = blockIdx.y * 128, colBase = blockIdx.x * 256;
    const int wm = (wid & 3) * 32, wn = (wid >> 2) * 64;

    const __half* Ag = g_xh  + (size_t)rowBase * Ddim;
    const __half* Bg = g_W1h + (size_t)colBase * Ddim;

    int ld_arr[6], ld_row[6], ld_off[6];
    uint32_t ld_saddr[6];
#pragma unroll
    for (int i = 0; i < 6; i++) {
        int c = tid + 512 * i;
        if (c < 1024) {
            ld_arr[i] = 0;
            ld_row[i] = c >> 3;
            ld_off[i] = (c & 7) * 8;
            ld_saddr[i] = sbase + (uint32_t)(ld_row[i] * LDAh + ld_off[i]) * 2;
        } else {
            int d = c - 1024;
            ld_arr[i] = 1;
            ld_row[i] = d >> 3;
            ld_off[i] = (d & 7) * 8;
            ld_saddr[i] = sbase + (uint32_t)(A_H + ld_row[i] * LDAh + ld_off[i]) * 2;
        }
    }

    const int a_m = wm + (lane & 15);
    const int a_k = ((lane >> 4) & 1) * 8;
    const uint32_t aOff0 = (uint32_t)(a_m * LDAh + a_k) * 2;
    const uint32_t aOff1 = (uint32_t)((a_m + 16) * LDAh + a_k) * 2;
    uint32_t bOff[4];
#pragma unroll
    for (int p = 0; p < 4; p++) {
        int n = wn + p * 16 + (lane & 7) + ((lane >> 4) & 1) * 8;
        bOff[p] = (uint32_t)(A_H + n * LDAh + ((lane >> 3) & 1) * 8) * 2;
    }

    float acc[2][8][4];
#pragma unroll
    for (int mt = 0; mt < 2; mt++)
#pragma unroll
        for (int nt = 0; nt < 8; nt++)
#pragma unroll
            for (int r = 0; r < 4; r++) acc[mt][nt][r] = 0.0f;

    const int NCHUNK = Ddim / BKh;   // 64
    const uint32_t stgB[3] = {0u, (uint32_t)STG_H * 2, (uint32_t)(2 * STG_H) * 2};

#pragma unroll
    for (int kc = 0; kc < NSTAGE - 1; kc++) {
        const int k0 = kc * BKh;
#pragma unroll
        for (int i = 0; i < 6; i++) {
            const __half* g = (ld_arr[i] ? Bg : Ag) +
                              (size_t)ld_row[i] * Ddim + k0 + ld_off[i];
            cp_async16(ld_saddr[i] + stgB[kc], g);
        }
        cp_commit();
    }

    int cur = 0, nxt = NSTAGE - 1;
    for (int kc = 0; kc < NCHUNK; kc++) {
        cp_wait<NSTAGE - 2>();
        __syncthreads();   // single barrier per chunk (stage nxt safe below)

        if (kc + NSTAGE - 1 < NCHUNK) {
            const int k0 = (kc + NSTAGE - 1) * BKh;
#pragma unroll
            for (int i = 0; i < 6; i++) {
                const __half* g = (ld_arr[i] ? Bg : Ag) +
                                  (size_t)ld_row[i] * Ddim + k0 + ld_off[i];
                cp_async16(ld_saddr[i] + stgB[nxt], g);
            }
            cp_commit();
        }

        const uint32_t sb = sbase + stgB[cur];
#pragma unroll
        for (int st = 0; st < 4; st++) {
            const uint32_t kb = (uint32_t)(st * 16) * 2;
            uint32_t a0[4], a1[4];
            ldsm_x4(a0, sb + aOff0 + kb);
            ldsm_x4(a1, sb + aOff1 + kb);
#pragma unroll
            for (int p = 0; p < 4; p++) {
                uint32_t bfr[4];
                ldsm_x4(bfr, sb + bOff[p] + kb);
                mma_fp16(acc[0][2 * p],     a0, bfr[0], bfr[1]);
                mma_fp16(acc[1][2 * p],     a1, bfr[0], bfr[1]);
                mma_fp16(acc[0][2 * p + 1], a0, bfr[2], bfr[3]);
                mma_fp16(acc[1][2 * p + 1], a1, bfr[2], bfr[3]);
            }
        }
        cur = (cur + 1 == NSTAGE) ? 0 : cur + 1;
        nxt = (nxt + 1 == NSTAGE) ? 0 : nxt + 1;
    }

    // ---- fused epilogue (smem reuse; barrier first: mainloop readers done) ----
    __syncthreads();
    const int g = lane >> 2, t = lane & 3;

    // (a) bias + silu -> fp16 h tile in smem [128][LDAe]
#pragma unroll
    for (int nt = 0; nt < 8; nt++) {
        const int n0 = wn + nt * 8 + t * 2;
        const float bs0 = b1[colBase + n0];
        const float bs1 = b1[colBase + n0 + 1];
#pragma unroll
        for (int mt = 0; mt < 2; mt++) {
            const int m0 = wm + mt * 16 + g;
            __half2 o0 = __floats2half2_rn(silu_f(acc[mt][nt][0] + bs0),
                                           silu_f(acc[mt][nt][1] + bs1));
            __half2 o1 = __floats2half2_rn(silu_f(acc[mt][nt][2] + bs0),
                                           silu_f(acc[mt][nt][3] + bs1));
            *(__half2*)(smh + (size_t)m0 * LDAe + n0)       = o0;
            *(__half2*)(smh + (size_t)(m0 + 8) * LDAe + n0) = o1;
        }
    }

    // (b) W2 slice [e][k] fp16
    __half* sW2e = smh + 128 * LDAe;
    for (int idx = tid; idx < 256 * Ed; idx += 512) {
        int kk = idx >> 6, e = idx & 63;
        sW2e[(size_t)e * LDAe + kk] =
            __float2half_rn(W2[(size_t)(colBase + kk) * Ed + e]);
    }
    __syncthreads();

    // (c) tensor-core partial-logit GEMM: m128 x n64 x k256
    const int mW = (wid & 3) * 32;
    const int nE = (wid >> 2) * 16;
    const uint32_t aO0 = (uint32_t)((mW + (lane & 15)) * LDAe +
                                    ((lane >> 4) & 1) * 8) * 2;
    const uint32_t aO1 = aO0 + (uint32_t)(16 * LDAe) * 2;
    const uint32_t bO = (uint32_t)(128 * LDAe +
                        (nE + (lane & 7) + ((lane >> 4) & 1) * 8) * LDAe +
                        ((lane >> 3) & 1) * 8) * 2;

    float pl[2][2][4];
#pragma unroll
    for (int mt = 0; mt < 2; mt++)
#pragma unroll
        for (int p = 0; p < 2; p++)
#pragma unroll
            for (int r = 0; r < 4; r++) pl[mt][p][r] = 0.0f;

#pragma unroll
    for (int st = 0; st < 16; st++) {
        const uint32_t kb = (uint32_t)(st * 16) * 2;
        uint32_t a0[4], a1[4], bf[4];
        ldsm_x4(a0, sbase + aO0 + kb);
        ldsm_x4(a1, sbase + aO1 + kb);
        ldsm_x4(bf, sbase + bO + kb);
        mma_fp16(pl[0][0], a0, bf[0], bf[1]);
        mma_fp16(pl[1][0], a1, bf[0], bf[1]);
        mma_fp16(pl[0][1], a0, bf[2], bf[3]);
        mma_fp16(pl[1][1], a1, bf[2], bf[3]);
    }

    // (d) store partial logits
#pragma unroll
    for (int mt = 0; mt < 2; mt++) {
#pragma unroll
        for (int p = 0; p < 2; p++) {
            const int row0 = rowBase + mW + mt * 16 + g;
            const int e0 = nE + p * 8 + t * 2;
            float2 v0 = make_float2(pl[mt][p][0], pl[mt][p][1]);
            float2 v1 = make_float2(pl[mt][p][2], pl[mt][p][3]);
            *(float2*)&g_plog[((size_t)blockIdx.x * Bdim + row0) * Ed + e0]     = v0;
            *(float2*)&g_plog[((size_t)blockIdx.x * Bdim + row0 + 8) * Ed + e0] = v1;
        }
    }
}

// ---------------------------------------------------------------------------
// router_reduce: sum 8 slices + b2; top-2 / softmax / prob partials / flags.
// ---------------------------------------------------------------------------
__global__ __launch_bounds__(256)
void router_reduce(const float* __restrict__ b2,
                   float* __restrict__ outW,
                   float* __restrict__ outI) {
    __shared__ float sProb[32][Ed];
    const int tid  = threadIdx.x;
    const int warp = tid >> 5;
    const int lane = tid & 31;
    const int rowBase = blockIdx.x * 32;

    const float b2a = b2[lane * 2];
    const float b2b = b2[lane * 2 + 1];

#pragma unroll
    for (int r = 0; r < 4; r++) {
        const int lrow = warp * 4 + r;
        const int row = rowBase + lrow;

        float l0 = b2a, l1 = b2b;
#pragma unroll
        for (int s = 0; s < NSLC; s++) {
            float2 v = *(const float2*)&g_plog[((size_t)s * Bdim + row) * Ed + lane * 2];
            l0 += v.x; l1 += v.y;
        }
        const int id0 = lane * 2, id1 = lane * 2 + 1;

        float bvv, sv; int bi, si;
        if (l0 >= l1) { bvv = l0; bi = id0; sv = l1; si = id1; }
        else          { bvv = l1; bi = id1; sv = l0; si = id0; }

        float v1 = bvv; int i1 = bi;
#pragma unroll
        for (int off = 16; off; off >>= 1) {
            float ov = __shfl_down_sync(0xffffffffu, v1, off);
            int   oi = __shfl_down_sync(0xffffffffu, i1, off);
            if (ov > v1 || (ov == v1 && oi < i1)) { v1 = ov; i1 = oi; }
        }
        v1 = __shfl_sync(0xffffffffu, v1, 0);
        i1 = __shfl_sync(0xffffffffu, i1, 0);

        float cv; int ci;
        if (bi == i1) { cv = sv; ci = si; } else { cv = bvv; ci = bi; }
        float v2 = cv; int i2 = ci;
#pragma unroll
        for (int off = 16; off; off >>= 1) {
            float ov = __shfl_down_sync(0xffffffffu, v2, off);
            int   oi = __shfl_down_sync(0xffffffffu, i2, off);
            if (ov > v2 || (ov == v2 && oi < i2)) { v2 = ov; i2 = oi; }
        }
        v2 = __shfl_sync(0xffffffffu, v2, 0);
        i2 = __shfl_sync(0xffffffffu, i2, 0);

        float v3 = -1e30f;
        if (id0 != i1 && id0 != i2) v3 = l0;
        if (id1 != i1 && id1 != i2 && l1 > v3) v3 = l1;
#pragma unroll
        for (int off = 16; off; off >>= 1) {
            float ov = __shfl_down_sync(0xffffffffu, v3, off);
            if (ov > v3) v3 = ov;
        }

        float p0 = expf(l0 - v1);
        float p1 = expf(l1 - v1);
        float ssum = p0 + p1;
#pragma unroll
        for (int off = 16; off; off >>= 1) ssum += __shfl_down_sync(0xffffffffu, ssum, off);
        ssum = __shfl_sync(0xffffffffu, ssum, 0);
        float inv = 1.0f / ssum;
        sProb[lrow][lane * 2]     = p0 * inv;
        sProb[lrow][lane * 2 + 1] = p1 * inv;

        if (lane == 0) {
            float d = expf(v2 - v1);
            float w0 = 1.0f / (1.0f + d);
            float w1 = d / (1.0f + d);
            outW[(size_t)row * 2]     = w0;
            outW[(size_t)row * 2 + 1] = w1;
            outI[(size_t)row * 2]     = (float)i1;
            outI[(size_t)row * 2 + 1] = (float)i2;
            g_top1[row]               = i1;
            if ((v1 - v2) < TAU || (v2 - v3) < TAU) {
                int pos = atomicAdd(&g_fixcount, 1);
                if (pos < FIXCAP) g_fixlist[pos] = row;
            }
        }
    }
    __syncthreads();

    if (tid < Ed) {
        float ps = 0.0f;
#pragma unroll
        for (int r = 0; r < 32; r++) ps += sProb[r][tid];
        g_pprob[(size_t)blockIdx.x * Ed + tid] = ps;
    }
}

// ---------------------------------------------------------------------------
// Fixup stage 1 (v2): exact fp32 h for flagged rows -> g_Hfix (compact).
// ---------------------------------------------------------------------------
__global__ __launch_bounds__(128)
void fixup_h(const float* __restrict__ x,
             const float* __restrict__ W1,
             const float* __restrict__ b1) {
    extern __shared__ unsigned long long sXP[];   // [1024][8]
    int cnt = g_fixcount; if (cnt > FIXCAP) cnt = FIXCAP;
    if (blockIdx.x * 16 >= cnt) return;
    const int tid = threadIdx.x;
    const int col = blockIdx.y * 512 + tid * 4;

    int rows[16];
#pragma unroll
    for (int r = 0; r < 16; r++) {
        int gi = blockIdx.x * 16 + r;
        rows[r] = g_fixlist[gi < cnt ? gi : cnt - 1];
    }

    unsigned long long acc2[8][4];
#pragma unroll
    for (int p = 0; p < 8; p++)
#pragma unroll
        for (int c = 0; c < 4; c++) acc2[p][c] = 0ULL;

    for (int q = 0; q < 4; q++) {
        __syncthreads();
        for (int idx = tid; idx < 8 * 1024; idx += 128) {
            int p = idx >> 10, kk = idx & 1023;
            float xa = x[(size_t)rows[2 * p]     * Ddim + q * 1024 + kk];
            float xb = x[(size_t)rows[2 * p + 1] * Ddim + q * 1024 + kk];
            sXP[(size_t)kk * 8 + p] = pack2(xa, xb);
        }
        __syncthreads();
        for (int kk = 0; kk < 1024; kk++) {
            float4 w = *(const float4*)&W1[(size_t)(q * 1024 + kk) * HIDd + col];
            unsigned long long wq[4];
            wq[0] = pack2(w.x, w.x); wq[1] = pack2(w.y, w.y);
            wq[2] = pack2(w.z, w.z); wq[3] = pack2(w.w, w.w);
            const unsigned long long* xp = &sXP[(size_t)kk * 8];
#pragma unroll
            for (int p = 0; p < 8; p++) {
                unsigned long long xv = xp[p];
                acc2[p][0] = fma2(xv, wq[0], acc2[p][0]);
                acc2[p][1] = fma2(xv, wq[1], acc2[p][1]);
                acc2[p][2] = fma2(xv, wq[2], acc2[p][2]);
                acc2[p][3] = fma2(xv, wq[3], acc2[p][3]);
            }
        }
    }

    float4 bb = *(const float4*)&b1[col];
    const float* bbp = (const float*)&bb;
#pragma unroll
    for (int p = 0; p < 8; p++) {
        int gi0 = blockIdx.x * 16 + 2 * p;
        int gi1 = gi0 + 1;
#pragma unroll
        for (int c = 0; c < 4; c++) {
            float2 v = unpack2(acc2[p][c]);
            if (gi0 < cnt) g_Hfix[(size_t)gi0 * HIDd + col + c] = silu_f(v.x + bbp[c]);
            if (gi1 < cnt) g_Hfix[(size_t)gi1 * HIDd + col + c] = silu_f(v.y + bbp[c]);
        }
    }
}

// ---------------------------------------------------------------------------
// Fixup stage 2: exact logits + top2 + weights; 4 independent k-accumulators.
// ---------------------------------------------------------------------------
__global__ __launch_bounds__(256)
void fixup_logits(const float* __restrict__ W2,
                  const float* __restrict__ b2,
                  float* __restrict__ outW,
                  float* __restrict__ outI) {
    int cnt = g_fixcount; if (cnt > FIXCAP) cnt = FIXCAP;
    const int fi = blockIdx.x;
    if (fi >= cnt) return;
    const int row = g_fixlist[fi];
    const int tid = threadIdx.x;
    const int e = tid & 63, q = tid >> 6;
    __shared__ float part[4][Ed];
    __shared__ float sLog[Ed];

    float a0 = 0.0f, a1 = 0.0f, a2 = 0.0f, a3 = 0.0f;
    const float* hrow = g_Hfix + (size_t)fi * HIDd;
    const int kb = q * 512;
#pragma unroll 4
    for (int k = 0; k < 512; k += 4) {
        a0 = fmaf(hrow[kb + k],     W2[(size_t)(kb + k)     * Ed + e], a0);
        a1 = fmaf(hrow[kb + k + 1], W2[(size_t)(kb + k + 1) * Ed + e], a1);
        a2 = fmaf(hrow[kb + k + 2], W2[(size_t)(kb + k + 2) * Ed + e], a2);
        a3 = fmaf(hrow[kb + k + 3], W2[(size_t)(kb + k + 3) * Ed + e], a3);
    }
    part[q][e] = (a0 + a1) + (a2 + a3);
    __syncthreads();
    if (tid < Ed)
        sLog[tid] = part[0][tid] + part[1][tid] + part[2][tid] + part[3][tid] + b2[tid];
    __syncthreads();
    if (tid == 0) {
        float v1 = -1e30f, v2 = -1e30f; int i1 = 0, i2 = 0;
        for (int j = 0; j < Ed; j++) {
            float v = sLog[j];
            if (v > v1)      { v2 = v1; i2 = i1; v1 = v; i1 = j; }
            else if (v > v2) { v2 = v;  i2 = j; }
        }
        float d = expf(v2 - v1);
        outW[(size_t)row * 2]     = 1.0f / (1.0f + d);
        outW[(size_t)row * 2 + 1] = d / (1.0f + d);
        outI[(size_t)row * 2]     = (float)i1;
        outI[(size_t)row * 2 + 1] = (float)i2;
        g_top1[row] = i1;
    }
}

// ---------------------------------------------------------------------------
__global__ __launch_bounds__(256)
void aux_final(float* __restrict__ outAux) {
    __shared__ int   hist[Ed];
    __shared__ float pp[4][Ed];
    __shared__ float term[Ed];
    const int tid = threadIdx.x;
    const int e = tid & 63, q = tid >> 6;
    if (tid < Ed) hist[tid] = 0;
    __syncthreads();
    for (int r = tid; r < Bdim; r += 256)
        atomicAdd(&hist[g_top1[r]], 1);

    float p = 0.0f;
    for (int b = q * 128; b < (q + 1) * 128; b++)
        p += g_pprob[b * Ed + e];
    pp[q][e] = p;
    __syncthreads();
    if (tid < Ed) {
        float psum = pp[0][tid] + pp[1][tid] + pp[2][tid] + pp[3][tid];
        term[tid] = ((float)hist[tid] * (1.0f / (float)Bdim)) *
                    (psum * (1.0f / (float)Bdim));
    }
    __syncthreads();
    if (tid == 0) {
        float s = 0.0f;
        for (int ee = 0; ee < Ed; ee++) s += term[ee];
        outAux[0] = (float)Ed * s;
    }
}

// ---------------------------------------------------------------------------
extern "C" void kernel_launch(void* const* d_in, const int* in_sizes, int n_in,
                              void* d_out, int out_size) {
    const float* x  = (const float*)d_in[0];
    const float* W1 = (const float*)d_in[1];
    const float* b1 = (const float*)d_in[2];
    const float* W2 = (const float*)d_in[3];
    const float* b2 = (const float*)d_in[4];
    float* out = (float*)d_out;

    float* outW   = out;
    float* outI   = out + 2 * Bdim;
    float* outAux = out + 4 * Bdim;

    cudaFuncSetAttribute(gemm1_fused, cudaFuncAttributeMaxDynamicSharedMemorySize,
                         SMEM_G1);
    cudaFuncSetAttribute(fixup_h, cudaFuncAttributeMaxDynamicSharedMemorySize,
                         8 * 1024 * 8);

    cvt_x<<<(int)(((size_t)Bdim * Ddim) / 8 / 256), 256>>>(x);
    transpose_W1h<<<dim3(HIDd / 32, Ddim / 32), 256>>>(W1);
    gemm1_fused<<<dim3(HIDd / 256, Bdim / 128), 512, SMEM_G1>>>(b1, W2);
    router_reduce<<<Bdim / 32, 256>>>(b2, outW, outI);
    fixup_h<<<dim3(FIXCAP / 16, 4), 128, 8 * 1024 * 8>>>(x, W1, b1);
    fixup_logits<<<FIXCAP, 256>>>(W2, b2, outW, outI);
    aux_final<<<1, 256>>>(outAux);
}

// round 16
// speedup vs baseline: 1.1881x; 1.1881x over previous
#include <cuda_runtime.h>
#include <cuda_fp16.h>
#include <cstdint>
#include <math.h>

// ---------------------------------------------------------------------------
// ExpertRouter: h = silu(x@W1+b1); logits = h@W2+b2; top-2 softmax + aux loss.
// B=16384, D=4096, HID=2048, E=64.
// GEMM1: fp16 mma, CTA 128x256, warp 32x64, cp.async 3-stage, fp32 h (R9).
// router_tc: standalone tensor-core logit GEMM (h,W2 -> fp16 in smem) +
// top-2/softmax/flags. Near-tie rows (gap < TAU) recomputed exactly in fp32.
// Output layout (f32): [weights B*2 | top_idx(as float) B*2 | aux].
// ---------------------------------------------------------------------------

#define Bdim 16384
#define Ddim 4096
#define HIDd 2048
#define Ed   64
#define TAU  3e-3f
#define FIXCAP 4096
#define NBLK_R (Bdim / 64)     // 256 router CTAs

__device__ float  g_H[(size_t)Bdim * HIDd];     // 134 MB intermediate h (fp32)
__device__ __half g_xh[(size_t)Bdim * Ddim];    // 134 MB x in fp16
__device__ __half g_W1h[(size_t)HIDd * Ddim];   // 16.8 MB W1^T in fp16
__device__ float  g_pprob[NBLK_R * Ed];
__device__ int    g_top1[Bdim];
__device__ int    g_fixcount;
__device__ int    g_fixlist[FIXCAP];

// ---- helpers ----
__device__ __forceinline__ float silu_f(float v) { return v / (1.0f + expf(-v)); }

__device__ __forceinline__ uint32_t smem_u32(const void* p) {
    uint32_t a;
    asm("{ .reg .u64 t; cvta.to.shared.u64 t, %1; cvt.u32.u64 %0, t; }" : "=r"(a) : "l"(p));
    return a;
}
__device__ __forceinline__ void cp_async16(uint32_t saddr, const void* gaddr) {
    asm volatile("cp.async.cg.shared.global [%0], [%1], 16;" :: "r"(saddr), "l"(gaddr));
}
__device__ __forceinline__ void cp_commit() {
    asm volatile("cp.async.commit_group;");
}
template <int N>
__device__ __forceinline__ void cp_wait() {
    asm volatile("cp.async.wait_group %0;" :: "n"(N));
}
__device__ __forceinline__ void ldsm_x4(uint32_t r[4], uint32_t saddr) {
    asm volatile("ldmatrix.sync.aligned.m8n8.x4.shared.b16 {%0,%1,%2,%3}, [%4];"
                 : "=r"(r[0]), "=r"(r[1]), "=r"(r[2]), "=r"(r[3]) : "r"(saddr));
}
__device__ __forceinline__ void mma_fp16(float c[4], const uint32_t a[4],
                                         uint32_t b0, uint32_t b1) {
    asm("mma.sync.aligned.m16n8k16.row.col.f32.f16.f16.f32 "
        "{%0,%1,%2,%3}, {%4,%5,%6,%7}, {%8,%9}, {%0,%1,%2,%3};"
        : "+f"(c[0]), "+f"(c[1]), "+f"(c[2]), "+f"(c[3])
        : "r"(a[0]), "r"(a[1]), "r"(a[2]), "r"(a[3]), "r"(b0), "r"(b1));
}

// ---- packed f32x2 ----
__device__ __forceinline__ unsigned long long pack2(float lo, float hi) {
    unsigned long long r;
    asm("mov.b64 %0, {%1, %2};" : "=l"(r) : "f"(lo), "f"(hi));
    return r;
}
__device__ __forceinline__ unsigned long long fma2(unsigned long long a,
                                                   unsigned long long b,
                                                   unsigned long long c) {
    unsigned long long d;
    asm("fma.rn.f32x2 %0, %1, %2, %3;" : "=l"(d) : "l"(a), "l"(b), "l"(c));
    return d;
}
__device__ __forceinline__ float2 unpack2(unsigned long long v) {
    float2 f;
    asm("mov.b64 {%0, %1}, %2;" : "=f"(f.x), "=f"(f.y) : "l"(v));
    return f;
}

// ---------------------------------------------------------------------------
__global__ __launch_bounds__(256)
void cvt_x(const float* __restrict__ x) {
    if (blockIdx.x == 0 && threadIdx.x == 0) g_fixcount = 0;
    size_t i = ((size_t)blockIdx.x * 256 + threadIdx.x) * 8;
    float4 f0 = *(const float4*)(x + i);
    float4 f1 = *(const float4*)(x + i + 4);
    __half2 h0 = __floats2half2_rn(f0.x, f0.y);
    __half2 h1 = __floats2half2_rn(f0.z, f0.w);
    __half2 h2 = __floats2half2_rn(f1.x, f1.y);
    __half2 h3 = __floats2half2_rn(f1.z, f1.w);
    uint4 o;
    o.x = *(uint32_t*)&h0; o.y = *(uint32_t*)&h1;
    o.z = *(uint32_t*)&h2; o.w = *(uint32_t*)&h3;
    *(uint4*)(g_xh + i) = o;
}

// ---------------------------------------------------------------------------
__global__ __launch_bounds__(256)
void transpose_W1h(const float* __restrict__ W1) {
    __shared__ float s[32][33];
    const int n0 = blockIdx.x * 32;
    const int k0 = blockIdx.y * 32;
    const int tx = threadIdx.x & 31;
    const int ty = (threadIdx.x >> 5) * 4;
#pragma unroll
    for (int i = 0; i < 4; i++)
        s[ty + i][tx] = W1[(size_t)(k0 + ty + i) * HIDd + n0 + tx];
    __syncthreads();
#pragma unroll
    for (int i = 0; i < 4; i++)
        g_W1h[(size_t)(n0 + ty + i) * Ddim + k0 + tx] = __float2half_rn(s[tx][ty + i]);
}

// ---------------------------------------------------------------------------
// GEMM1 (R9-exact): H = silu(x @ W1 + b1). CTA 128m x 256n, 16 warps,
// warp tile 32m x 64n, BK=64, cp.async 3-stage, ldmatrix. h -> fp32.
// ---------------------------------------------------------------------------
#define BKh 64
#define LDAh 72
#define A_H (128 * LDAh)
#define B_H (256 * LDAh)
#define STG_H (A_H + B_H)
#define NSTAGE 3
#define SMEM_G1 (NSTAGE * STG_H * 2)

__global__ __launch_bounds__(512, 1)
void gemm1_fp16(const float* __restrict__ b1) {
    extern __shared__ __half smh[];
    const uint32_t sbase = smem_u32(smh);

    const int tid = threadIdx.x;
    const int wid = tid >> 5, lane = tid & 31;
    const int rowBase = blockIdx.y * 128, colBase = blockIdx.x * 256;
    const int wm = (wid & 3) * 32, wn = (wid >> 2) * 64;

    const __half* Ag = g_xh  + (size_t)rowBase * Ddim;
    const __half* Bg = g_W1h + (size_t)colBase * Ddim;

    int ld_arr[6], ld_row[6], ld_off[6];
    uint32_t ld_saddr[6];
#pragma unroll
    for (int i = 0; i < 6; i++) {
        int c = tid + 512 * i;
        if (c < 1024) {
            ld_arr[i] = 0;
            ld_row[i] = c >> 3;
            ld_off[i] = (c & 7) * 8;
            ld_saddr[i] = sbase + (uint32_t)(ld_row[i] * LDAh + ld_off[i]) * 2;
        } else {
            int d = c - 1024;
            ld_arr[i] = 1;
            ld_row[i] = d >> 3;
            ld_off[i] = (d & 7) * 8;
            ld_saddr[i] = sbase + (uint32_t)(A_H + ld_row[i] * LDAh + ld_off[i]) * 2;
        }
    }

    const int a_m = wm + (lane & 15);
    const int a_k = ((lane >> 4) & 1) * 8;
    const uint32_t aOff0 = (uint32_t)(a_m * LDAh + a_k) * 2;
    const uint32_t aOff1 = (uint32_t)((a_m + 16) * LDAh + a_k) * 2;
    uint32_t bOff[4];
#pragma unroll
    for (int p = 0; p < 4; p++) {
        int n = wn + p * 16 + (lane & 7) + ((lane >> 4) & 1) * 8;
        bOff[p] = (uint32_t)(A_H + n * LDAh + ((lane >> 3) & 1) * 8) * 2;
    }

    float acc[2][8][4];
#pragma unroll
    for (int mt = 0; mt < 2; mt++)
#pragma unroll
        for (int nt = 0; nt < 8; nt++)
#pragma unroll
            for (int r = 0; r < 4; r++) acc[mt][nt][r] = 0.0f;

    const int NCHUNK = Ddim / BKh;
    const uint32_t stgB[3] = {0u, (uint32_t)STG_H * 2, (uint32_t)(2 * STG_H) * 2};

#pragma unroll
    for (int kc = 0; kc < NSTAGE - 1; kc++) {
        const int k0 = kc * BKh;
#pragma unroll
        for (int i = 0; i < 6; i++) {
            const __half* g = (ld_arr[i] ? Bg : Ag) +
                              (size_t)ld_row[i] * Ddim + k0 + ld_off[i];
            cp_async16(ld_saddr[i] + stgB[kc], g);
        }
        cp_commit();
    }

    int cur = 0, nxt = NSTAGE - 1;
    for (int kc = 0; kc < NCHUNK; kc++) {
        cp_wait<NSTAGE - 2>();
        __syncthreads();

        if (kc + NSTAGE - 1 < NCHUNK) {
            const int k0 = (kc + NSTAGE - 1) * BKh;
#pragma unroll
            for (int i = 0; i < 6; i++) {
                const __half* g = (ld_arr[i] ? Bg : Ag) +
                                  (size_t)ld_row[i] * Ddim + k0 + ld_off[i];
                cp_async16(ld_saddr[i] + stgB[nxt], g);
            }
            cp_commit();
        }

        const uint32_t sb = sbase + stgB[cur];
#pragma unroll
        for (int st = 0; st < 4; st++) {
            const uint32_t kb = (uint32_t)(st * 16) * 2;
            uint32_t a0[4], a1[4];
            ldsm_x4(a0, sb + aOff0 + kb);
            ldsm_x4(a1, sb + aOff1 + kb);
#pragma unroll
            for (int p = 0; p < 4; p++) {
                uint32_t bfr[4];
                ldsm_x4(bfr, sb + bOff[p] + kb);
                mma_fp16(acc[0][2 * p],     a0, bfr[0], bfr[1]);
                mma_fp16(acc[1][2 * p],     a1, bfr[0], bfr[1]);
                mma_fp16(acc[0][2 * p + 1], a0, bfr[2], bfr[3]);
                mma_fp16(acc[1][2 * p + 1], a1, bfr[2], bfr[3]);
            }
        }
        __syncthreads();
        cur = (cur + 1 == NSTAGE) ? 0 : cur + 1;
        nxt = (nxt + 1 == NSTAGE) ? 0 : nxt + 1;
    }

    const int g = lane >> 2, t = lane & 3;
#pragma unroll
    for (int nt = 0; nt < 8; nt++) {
        const int n0 = colBase + wn + nt * 8 + t * 2;
        const float bs0 = b1[n0];
        const float bs1 = b1[n0 + 1];
#pragma unroll
        for (int mt = 0; mt < 2; mt++) {
            const int m0 = rowBase + wm + mt * 16 + g;
            float2 o0, o1;
            o0.x = silu_f(acc[mt][nt][0] + bs0);
            o0.y = silu_f(acc[mt][nt][1] + bs1);
            o1.x = silu_f(acc[mt][nt][2] + bs0);
            o1.y = silu_f(acc[mt][nt][3] + bs1);
            *(float2*)(g_H + (size_t)m0 * HIDd + n0)       = o0;
            *(float2*)(g_H + (size_t)(m0 + 8) * HIDd + n0) = o1;
        }
    }
}

// ---------------------------------------------------------------------------
// router_tc: logits = H @ W2 + b2 on tensor cores (h,W2 -> fp16 in smem);
// top-2 / softmax / prob partials / tie flags.
// 64 rows/CTA, 256 thr (8 warps: 4m x 2n; warp tile 16m x 32e), grid = 256.
// smem (dynamic): hT[64][LDR] | w2T[64][LDR] | sLog[64][64] | sProb[64][64]
// ---------------------------------------------------------------------------
#define LDR 136
#define RT_HT    0
#define RT_W2T   (64 * LDR * 2)                  // 17408 B
#define RT_SLOG  (2 * 64 * LDR * 2)              // 34816 B
#define RT_SPROB (RT_SLOG + 64 * 64 * 4)         // 51200 B
#define SMEM_RT  (RT_SPROB + 64 * 64 * 4)        // 67584 B

__global__ __launch_bounds__(256)
void router_tc(const float* __restrict__ W2,
               const float* __restrict__ b2,
               float* __restrict__ outW,
               float* __restrict__ outI) {
    extern __shared__ char smr[];
    const uint32_t sbase = smem_u32(smr);
    __half* hT  = (__half*)(smr + RT_HT);
    __half* w2T = (__half*)(smr + RT_W2T);
    float*  sLog  = (float*)(smr + RT_SLOG);
    float*  sProb = (float*)(smr + RT_SPROB);

    const int tid  = threadIdx.x;
    const int wid  = tid >> 5;
    const int lane = tid & 31;
    const int rowBase = blockIdx.x * 64;
    const int wm = (wid & 3) * 16;     // 4 m-warps x 16 rows
    const int wn = (wid >> 2) * 32;    // 2 n-warps x 32 experts

    // ldsm lane addresses (byte offsets within smem block)
    const uint32_t aOff = sbase + RT_HT +
        (uint32_t)((wm + (lane & 15)) * LDR + ((lane >> 4) & 1) * 8) * 2;
    uint32_t bOff[2];
#pragma unroll
    for (int p = 0; p < 2; p++) {
        int n = wn + p * 16 + (lane & 7) + ((lane >> 4) & 1) * 8;
        bOff[p] = sbase + RT_W2T +
            (uint32_t)(n * LDR + ((lane >> 3) & 1) * 8) * 2;
    }

    float acc[4][4];
#pragma unroll
    for (int nb = 0; nb < 4; nb++)
#pragma unroll
        for (int r = 0; r < 4; r++) acc[nb][r] = 0.0f;

    for (int kc = 0; kc < HIDd; kc += 128) {
        __syncthreads();
        // h chunk: 64 rows x 128 k, fp32 -> fp16
#pragma unroll
        for (int i = 0; i < 8; i++) {
            int idx = tid + 256 * i;                 // 0..2047 float4s
            int r = idx >> 5, c = (idx & 31) * 4;
            float4 v = *(const float4*)&g_H[(size_t)(rowBase + r) * HIDd + kc + c];
            __half2 p0 = __floats2half2_rn(v.x, v.y);
            __half2 p1 = __floats2half2_rn(v.z, v.w);
            uint32_t* d = (uint32_t*)(hT + r * LDR + c);
            d[0] = *(uint32_t*)&p0;
            d[1] = *(uint32_t*)&p1;
        }
        // W2 chunk: [128 k][64 e] -> w2T[e][k] fp16
#pragma unroll
        for (int i = 0; i < 32; i++) {
            int idx = tid + 256 * i;                 // 0..8191
            int kk = idx >> 6, e = idx & 63;
            w2T[e * LDR + kk] = __float2half_rn(W2[(size_t)(kc + kk) * Ed + e]);
        }
        __syncthreads();

#pragma unroll
        for (int st = 0; st < 8; st++) {
            const uint32_t kb = (uint32_t)(st * 16) * 2;
            uint32_t a[4], b0[4], b1v[4];
            ldsm_x4(a, aOff + kb);
            ldsm_x4(b0, bOff[0] + kb);
            ldsm_x4(b1v, bOff[1] + kb);
            mma_fp16(acc[0], a, b0[0], b0[1]);
            mma_fp16(acc[1], a, b0[2], b0[3]);
            mma_fp16(acc[2], a, b1v[0], b1v[1]);
            mma_fp16(acc[3], a, b1v[2], b1v[3]);
        }
    }

    // write logits to sLog (hT/w2T dead after this barrier)
    __syncthreads();
    {
        const int g = lane >> 2, t = lane & 3;
#pragma unroll
        for (int nb = 0; nb < 4; nb++) {
            const int col = wn + nb * 8 + t * 2;
            *(float2*)&sLog[(wm + g) * 64 + col]     = make_float2(acc[nb][0], acc[nb][1]);
            *(float2*)&sLog[(wm + g + 8) * 64 + col] = make_float2(acc[nb][2], acc[nb][3]);
        }
    }
    __syncthreads();

    // top-2 / softmax / flags: warp w handles rows w*8 .. w*8+7
    const float b2a = b2[lane * 2];
    const float b2b = b2[lane * 2 + 1];

#pragma unroll
    for (int r = 0; r < 8; r++) {
        const int lrow = wid * 8 + r;
        const int row = rowBase + lrow;
        float l0 = sLog[lrow * 64 + lane * 2]     + b2a;
        float l1 = sLog[lrow * 64 + lane * 2 + 1] + b2b;
        const int id0 = lane * 2, id1 = lane * 2 + 1;

        float bvv, sv; int bi, si;
        if (l0 >= l1) { bvv = l0; bi = id0; sv = l1; si = id1; }
        else          { bvv = l1; bi = id1; sv = l0; si = id0; }

        float v1 = bvv; int i1 = bi;
#pragma unroll
        for (int off = 16; off; off >>= 1) {
            float ov = __shfl_down_sync(0xffffffffu, v1, off);
            int   oi = __shfl_down_sync(0xffffffffu, i1, off);
            if (ov > v1 || (ov == v1 && oi < i1)) { v1 = ov; i1 = oi; }
        }
        v1 = __shfl_sync(0xffffffffu, v1, 0);
        i1 = __shfl_sync(0xffffffffu, i1, 0);

        float cv; int ci;
        if (bi == i1) { cv = sv; ci = si; } else { cv = bvv; ci = bi; }
        float v2 = cv; int i2 = ci;
#pragma unroll
        for (int off = 16; off; off >>= 1) {
            float ov = __shfl_down_sync(0xffffffffu, v2, off);
            int   oi = __shfl_down_sync(0xffffffffu, i2, off);
            if (ov > v2 || (ov == v2 && oi < i2)) { v2 = ov; i2 = oi; }
        }
        v2 = __shfl_sync(0xffffffffu, v2, 0);
        i2 = __shfl_sync(0xffffffffu, i2, 0);

        float v3 = -1e30f;
        if (id0 != i1 && id0 != i2) v3 = l0;
        if (id1 != i1 && id1 != i2 && l1 > v3) v3 = l1;
#pragma unroll
        for (int off = 16; off; off >>= 1) {
            float ov = __shfl_down_sync(0xffffffffu, v3, off);
            if (ov > v3) v3 = ov;
        }

        float p0 = expf(l0 - v1);
        float p1 = expf(l1 - v1);
        float ssum = p0 + p1;
#pragma unroll
        for (int off = 16; off; off >>= 1) ssum += __shfl_down_sync(0xffffffffu, ssum, off);
        ssum = __shfl_sync(0xffffffffu, ssum, 0);
        float inv = 1.0f / ssum;
        sProb[lrow * 64 + lane * 2]     = p0 * inv;
        sProb[lrow * 64 + lane * 2 + 1] = p1 * inv;

        if (lane == 0) {
            float d = expf(v2 - v1);
            float w0 = 1.0f / (1.0f + d);
            float w1 = d / (1.0f + d);
            outW[(size_t)row * 2]     = w0;
            outW[(size_t)row * 2 + 1] = w1;
            outI[(size_t)row * 2]     = (float)i1;
            outI[(size_t)row * 2 + 1] = (float)i2;
            g_top1[row]               = i1;
            if ((v1 - v2) < TAU || (v2 - v3) < TAU) {
                int pos = atomicAdd(&g_fixcount, 1);
                if (pos < FIXCAP) g_fixlist[pos] = row;
            }
        }
    }
    __syncthreads();

    if (tid < Ed) {
        float ps = 0.0f;
#pragma unroll
        for (int r = 0; r < 64; r++) ps += sProb[r * 64 + tid];
        g_pprob[(size_t)blockIdx.x * Ed + tid] = ps;
    }
}

// ---------------------------------------------------------------------------
// Fixup stage 1 (v2, R9-exact): exact fp32 h for flagged rows -> g_H.
// ---------------------------------------------------------------------------
__global__ __launch_bounds__(128)
void fixup_h(const float* __restrict__ x,
             const float* __restrict__ W1,
             const float* __restrict__ b1) {
    extern __shared__ unsigned long long sXP[];   // [1024][8]
    int cnt = g_fixcount; if (cnt > FIXCAP) cnt = FIXCAP;
    if (blockIdx.x * 16 >= cnt) return;
    const int tid = threadIdx.x;
    const int col = blockIdx.y * 512 + tid * 4;

    int rows[16];
#pragma unroll
    for (int r = 0; r < 16; r++) {
        int gi = blockIdx.x * 16 + r;
        rows[r] = g_fixlist[gi < cnt ? gi : cnt - 1];
    }

    unsigned long long acc2[8][4];
#pragma unroll
    for (int p = 0; p < 8; p++)
#pragma unroll
        for (int c = 0; c < 4; c++) acc2[p][c] = 0ULL;

    for (int q = 0; q < 4; q++) {
        __syncthreads();
        for (int idx = tid; idx < 8 * 1024; idx += 128) {
            int p = idx >> 10, kk = idx & 1023;
            float xa = x[(size_t)rows[2 * p]     * Ddim + q * 1024 + kk];
            float xb = x[(size_t)rows[2 * p + 1] * Ddim + q * 1024 + kk];
            sXP[(size_t)kk * 8 + p] = pack2(xa, xb);
        }
        __syncthreads();
        for (int kk = 0; kk < 1024; kk++) {
            float4 w = *(const float4*)&W1[(size_t)(q * 1024 + kk) * HIDd + col];
            unsigned long long wq[4];
            wq[0] = pack2(w.x, w.x); wq[1] = pack2(w.y, w.y);
            wq[2] = pack2(w.z, w.z); wq[3] = pack2(w.w, w.w);
            const unsigned long long* xp = &sXP[(size_t)kk * 8];
#pragma unroll
            for (int p = 0; p < 8; p++) {
                unsigned long long xv = xp[p];
                acc2[p][0] = fma2(xv, wq[0], acc2[p][0]);
                acc2[p][1] = fma2(xv, wq[1], acc2[p][1]);
                acc2[p][2] = fma2(xv, wq[2], acc2[p][2]);
                acc2[p][3] = fma2(xv, wq[3], acc2[p][3]);
            }
        }
    }

    float4 bb = *(const float4*)&b1[col];
    const float* bbp = (const float*)&bb;
#pragma unroll
    for (int p = 0; p < 8; p++) {
        int gi0 = blockIdx.x * 16 + 2 * p;
        int gi1 = gi0 + 1;
#pragma unroll
        for (int c = 0; c < 4; c++) {
            float2 v = unpack2(acc2[p][c]);
            if (gi0 < cnt) g_H[(size_t)rows[2 * p]     * HIDd + col + c] = silu_f(v.x + bbp[c]);
            if (gi1 < cnt) g_H[(size_t)rows[2 * p + 1] * HIDd + col + c] = silu_f(v.y + bbp[c]);
        }
    }
}

// ---------------------------------------------------------------------------
// Fixup stage 2 (R9-exact): exact logits + top2 + weights for flagged rows.
// ---------------------------------------------------------------------------
__global__ __launch_bounds__(256)
void fixup_logits(const float* __restrict__ W2,
                  const float* __restrict__ b2,
                  float* __restrict__ outW,
                  float* __restrict__ outI) {
    int cnt = g_fixcount; if (cnt > FIXCAP) cnt = FIXCAP;
    const int fi = blockIdx.x;
    if (fi >= cnt) return;
    const int row = g_fixlist[fi];
    const int tid = threadIdx.x;
    const int e = tid & 63, q = tid >> 6;
    __shared__ float part[4][Ed];
    __shared__ float sLog[Ed];

    float a = 0.0f;
    const float* hrow = g_H + (size_t)row * HIDd;
    for (int k = q * 512; k < (q + 1) * 512; k++)
        a = fmaf(hrow[k], W2[(size_t)k * Ed + e], a);
    part[q][e] = a;
    __syncthreads();
    if (tid < Ed)
        sLog[tid] = part[0][tid] + part[1][tid] + part[2][tid] + part[3][tid] + b2[tid];
    __syncthreads();
    if (tid == 0) {
        float v1 = -1e30f, v2 = -1e30f; int i1 = 0, i2 = 0;
        for (int j = 0; j < Ed; j++) {
            float v = sLog[j];
            if (v > v1)      { v2 = v1; i2 = i1; v1 = v; i1 = j; }
            else if (v > v2) { v2 = v;  i2 = j; }
        }
        float d = expf(v2 - v1);
        outW[(size_t)row * 2]     = 1.0f / (1.0f + d);
        outW[(size_t)row * 2 + 1] = d / (1.0f + d);
        outI[(size_t)row * 2]     = (float)i1;
        outI[(size_t)row * 2 + 1] = (float)i2;
        g_top1[row] = i1;
    }
}

// ---------------------------------------------------------------------------
__global__ __launch_bounds__(256)
void aux_final(float* __restrict__ outAux) {
    __shared__ int   hist[Ed];
    __shared__ float pp[4][Ed];
    __shared__ float term[Ed];
    const int tid = threadIdx.x;
    const int e = tid & 63, q = tid >> 6;
    if (tid < Ed) hist[tid] = 0;
    __syncthreads();
    for (int r = tid; r < Bdim; r += 256)
        atomicAdd(&hist[g_top1[r]], 1);

    float p = 0.0f;
    for (int b = q * (NBLK_R / 4); b < (q + 1) * (NBLK_R / 4); b++)
        p += g_pprob[b * Ed + e];
    pp[q][e] = p;
    __syncthreads();
    if (tid < Ed) {
        float psum = pp[0][tid] + pp[1][tid] + pp[2][tid] + pp[3][tid];
        term[tid] = ((float)hist[tid] * (1.0f / (float)Bdim)) *
                    (psum * (1.0f / (float)Bdim));
    }
    __syncthreads();
    if (tid == 0) {
        float s = 0.0f;
        for (int ee = 0; ee < Ed; ee++) s += term[ee];
        outAux[0] = (float)Ed * s;
    }
}

// ---------------------------------------------------------------------------
extern "C" void kernel_launch(void* const* d_in, const int* in_sizes, int n_in,
                              void* d_out, int out_size) {
    const float* x  = (const float*)d_in[0];
    const float* W1 = (const float*)d_in[1];
    const float* b1 = (const float*)d_in[2];
    const float* W2 = (const float*)d_in[3];
    const float* b2 = (const float*)d_in[4];
    float* out = (float*)d_out;

    float* outW   = out;
    float* outI   = out + 2 * Bdim;
    float* outAux = out + 4 * Bdim;

    cudaFuncSetAttribute(gemm1_fp16, cudaFuncAttributeMaxDynamicSharedMemorySize,
                         SMEM_G1);
    cudaFuncSetAttribute(router_tc, cudaFuncAttributeMaxDynamicSharedMemorySize,
                         SMEM_RT);
    cudaFuncSetAttribute(fixup_h, cudaFuncAttributeMaxDynamicSharedMemorySize,
                         8 * 1024 * 8);

    cvt_x<<<(int)(((size_t)Bdim * Ddim) / 8 / 256), 256>>>(x);
    transpose_W1h<<<dim3(HIDd / 32, Ddim / 32), 256>>>(W1);
    gemm1_fp16<<<dim3(HIDd / 256, Bdim / 128), 512, SMEM_G1>>>(b1);
    router_tc<<<NBLK_R, 256, SMEM_RT>>>(W2, b2, outW, outI);
    fixup_h<<<dim3(FIXCAP / 16, 4), 128, 8 * 1024 * 8>>>(x, W1, b1);
    fixup_logits<<<FIXCAP, 256>>>(W2, b2, outW, outI);
    aux_final<<<1, 256>>>(outAux);
}